// round 16
// baseline (speedup 1.0000x reference)
#include <cuda_runtime.h>
#include <math.h>

// Problem constants
#define NN 16384
#define NB 64
#define NVOCAB 100
#define NL0 128
#define NH 64

// ---------------------------------------------------------------------------
// SINGLE fused kernel, grid = 64 + 32768. No scratch globals, no 2nd launch.
//
//  blocks [0, 64): MLP table + gather (correctness-verified in R11/R14:
//    ascending-k fma chain, serial ascending 64-add reduction, exact
//    reference rounding). ~11us, hidden under the 141us store stream.
//
//  blocks [64, 32832): adjacency. block -> (row, half).
//    Coarse reject (uniform, 3 L2-hot loads): sorted batch => if
//    batch[jbase] > b || batch[jbase+8191] < b, the half-row is all zeros
//    -> pure 8x STG.128 __stcs loop.
//    Otherwise: NO binary search, NO __syncthreads (R14 lesson: a 14-deep
//    dependent load chain behind a block barrier stalls all 8 warps before
//    any store; wave-synchronized it cost DRAM% 90->69, +35us). Instead the
//    per-chunk gate uses sortedness directly:
//        chunk [j0, j0+3] can contain batch b  iff
//        batch[j0] <= b && batch[j0+3] >= b
//    — two independent, L1-hot loads per chunk, overlapped with stores by
//    the 8-chunk ILP. Inner per-element test is exact integer equality
//    batch[j]==b (matches reference same_graph exactly); d2 uses the exact
//    reference rounding:
//      sq = (x*x + y*y) + z*z ;  d2 = (sq_i+sq_j) - 2*dot (ascending fma)
//
//  __stcs evict-first is MANDATORY (wall-clock A/B: wb 180.8 / stcs 151.2 /
//  stwt 153.6; single-pass ncu DRAM% inverted the ordering — trust replay
//  wall time). No __launch_bounds__ (occupancy was DRAM-neutral in R12).
//
//  batch dtype auto-detect: int64 LE layout has 32-bit word [NN-1]==0 (a
//  high word); int32 layout has it == max batch (~63).
// ---------------------------------------------------------------------------
__global__ void fused_final(const void* __restrict__ batch_raw,
                            const int*  __restrict__ z,
                            const float* __restrict__ pos,
                            const float* __restrict__ emb,
                            const float* __restrict__ w1,
                            const float* __restrict__ b1,
                            const float* __restrict__ w2,
                            const float* __restrict__ b2,
                            float*  __restrict__ out,
                            float4* __restrict__ adj)
{
    const int tid = threadIdx.x;

    if (blockIdx.x < 64) {
        // ---- MLP table + gather (self-contained per block) ----
        __shared__ float sh[256];
        __shared__ float table[NVOCAB];
        const int v4 = tid >> 6;      // 0..3: vocab within round
        const int j  = tid & 63;      // hidden unit
        const float b2v = b2[0];

        for (int r = 0; r < 25; r++) {
            const int vv = r * 4 + v4;
            const float* e = emb + (size_t)vv * NL0;
            float acc = b1[j];
#pragma unroll 8
            for (int k = 0; k < NL0; k++)
                acc = fmaf(e[k], w1[k * NH + j], acc);
            // silu(x) = x * sigmoid(x)
            float s = 1.0f / (1.0f + expf(-acc));
            sh[tid] = (acc * s) * w2[j];
            __syncthreads();
            if (tid < 4) {
                const float* p = sh + tid * 64;
                float o = 0.0f;
                for (int k = 0; k < 64; k++) o += p[k];   // ascending, serial
                table[r * 4 + tid] = o + b2v;
            }
            __syncthreads();
        }
        int i = blockIdx.x * 256 + tid;
        out[i] = table[z[i]];
        return;
    }

    // ---- adjacency ----
    const int abid = blockIdx.x - 64;
    const int row  = abid >> 1;
    const int half = abid & 1;

    const int* w32 = (const int*)batch_raw;
    const long long* w64 = (const long long*)batch_raw;
    const bool is32 = (w32[NN - 1] != 0);

    const int b = is32 ? w32[row] : (int)w64[row];
    const int jbase = half * 8192;
    const int bFirst = is32 ? w32[jbase]        : (int)w64[jbase];
    const int bLast  = is32 ? w32[jbase + 8191] : (int)w64[jbase + 8191];

    const unsigned cbase = (unsigned)row * 4096u + (unsigned)half * 2048u;
    const float4 zero = make_float4(0.f, 0.f, 0.f, 0.f);

    if (bFirst > b || bLast < b) {
        // Pure zero-fill fast path: 8x coalesced STG.128, nothing else
#pragma unroll
        for (int k = 0; k < 8; k++)
            __stcs(&adj[cbase + tid + k * 256], zero);
        return;
    }

    // ---- slow path: barrier-free, search-free ----
    const float xi = pos[3 * row + 0];
    const float yi = pos[3 * row + 1];
    const float zi = pos[3 * row + 2];
    const float sqi = __fadd_rn(__fadd_rn(__fmul_rn(xi, xi),
                                          __fmul_rn(yi, yi)),
                                __fmul_rn(zi, zi));

#pragma unroll
    for (int k = 0; k < 8; k++) {
        const int c  = tid + k * 256;        // chunk within half-row
        const int j0 = jbase + (c << 2);     // first element of chunk
        // Gate: chunk may contain batch b (sorted batch), 2 L1-hot loads
        const int b0 = is32 ? w32[j0]     : (int)w64[j0];
        const int b3 = is32 ? w32[j0 + 3] : (int)w64[j0 + 3];
        float4 v = zero;
        if (b0 <= b && b3 >= b) {            // ~97% of chunks skip
            float r[4];
#pragma unroll
            for (int e = 0; e < 4; e++) {
                const int jj = j0 + e;
                const int bj = (e == 0) ? b0 : (e == 3) ? b3
                              : (is32 ? w32[jj] : (int)w64[jj]);
                float val = 0.0f;
                if (bj == b && jj != row) {  // exact same_graph test
                    const float xj = pos[3 * jj + 0];
                    const float yj = pos[3 * jj + 1];
                    const float zj = pos[3 * jj + 2];
                    const float sqj = __fadd_rn(__fadd_rn(__fmul_rn(xj, xj),
                                                          __fmul_rn(yj, yj)),
                                                __fmul_rn(zj, zj));
                    const float dot = fmaf(zi, zj,
                                      fmaf(yi, yj,
                                           __fmul_rn(xi, xj)));
                    const float d2 = __fsub_rn(__fadd_rn(sqi, sqj),
                                               __fmul_rn(2.0f, dot));
                    val = (d2 < 64.0f) ? 1.0f : 0.0f;
                }
                r[e] = val;
            }
            v = make_float4(r[0], r[1], r[2], r[3]);
        }
        __stcs(&adj[cbase + c], v);
    }
}

// ---------------------------------------------------------------------------
extern "C" void kernel_launch(void* const* d_in, const int* in_sizes, int n_in,
                              void* d_out, int out_size) {
    const int*   z     = (const int*)d_in[0];
    const void*  batch = d_in[1];           // int32 or int64, device-detected
    const float* pos   = (const float*)d_in[2];
    const float* emb   = (const float*)d_in[3];
    const float* w1    = (const float*)d_in[4];
    const float* b1    = (const float*)d_in[5];
    const float* w2    = (const float*)d_in[6];
    const float* b2    = (const float*)d_in[7];
    float* out = (float*)d_out;

    fused_final<<<64 + 32768, 256>>>(batch, z, pos, emb, w1, b1, w2, b2,
                                     out, (float4*)(out + NN));
}

// round 17
// speedup vs baseline: 1.3948x; 1.3948x over previous
#include <cuda_runtime.h>
#include <math.h>

// Problem constants
#define NN 16384
#define NB 64
#define NVOCAB 100
#define NL0 128
#define NH 64

// Scratch (__device__ globals — no allocation allowed)
__device__ float g_px[NN], g_py[NN], g_pz[NN], g_sq[NN];
__device__ int2  g_band[NN];          // (lo, hi) packed: one 8B load per thread
__device__ float g_table[NVOCAB];

// ---------------------------------------------------------------------------
// CHAMPION CONFIGURATION (R9, 151.2us) — restored verbatim after the fusion
// axis was closed (R11: 190.9, R14: 186.4, R16: 209.4; all fused variants
// collapse the store stream to DRAM 60-69% for reasons the counters do not
// isolate — smem residency / gate-load L1 interference suspected).
//
// Kernel A: fused prep + MLP table.
//   blocks [0, 64):    prep — SoA pos split, sq, same-batch band via binary
//                      search on sorted batch (int32/int64 auto-detected).
//   blocks [64, 164):  MLP collapsed to 100-entry vocab table.
// ---------------------------------------------------------------------------
__global__ void fused_prep_mlp(const void* __restrict__ batch_raw,
                               const float* __restrict__ pos,
                               const float* __restrict__ emb,
                               const float* __restrict__ w1,
                               const float* __restrict__ b1,
                               const float* __restrict__ w2,
                               const float* __restrict__ b2) {
    if (blockIdx.x < 64) {
        // ---- prep ----
        int i = blockIdx.x * 256 + threadIdx.x;

        float x = pos[3 * i + 0];
        float y = pos[3 * i + 1];
        float z = pos[3 * i + 2];
        g_px[i] = x; g_py[i] = y; g_pz[i] = z;
        // sq: separate rounds, no fma contraction (matches XLA mul+add)
        g_sq[i] = __fadd_rn(__fadd_rn(__fmul_rn(x, x), __fmul_rn(y, y)),
                            __fmul_rn(z, z));

        // Detect batch dtype: int32 layout -> word [NN-1] = max batch (~63);
        // int64 LE layout -> word [NN-1] is a high word = 0.
        const int* w32 = (const int*)batch_raw;
        bool is32 = (w32[NN - 1] != 0);

        long long bi = is32 ? (long long)w32[i]
                            : ((const long long*)batch_raw)[i];

        // lower_bound
        int lo = 0, hi = NN;
        while (lo < hi) {
            int m = (lo + hi) >> 1;
            long long bm = is32 ? (long long)w32[m]
                                : ((const long long*)batch_raw)[m];
            if (bm < bi) lo = m + 1; else hi = m;
        }
        int lb = lo;
        // upper_bound
        lo = 0; hi = NN;
        while (lo < hi) {
            int m = (lo + hi) >> 1;
            long long bm = is32 ? (long long)w32[m]
                                : ((const long long*)batch_raw)[m];
            if (bm <= bi) lo = m + 1; else hi = m;
        }
        g_band[i] = make_int2(lb, lo);
    } else {
        // ---- MLP table: out depends on z only through emb[z]; 100 rows ----
        __shared__ float sh[NH];
        int v = blockIdx.x - 64;
        int j = threadIdx.x;

        if (j < NH) {
            const float* e = emb + (size_t)v * NL0;
            float acc = b1[j];
#pragma unroll 8
            for (int k = 0; k < NL0; k++)
                acc = fmaf(e[k], w1[k * NH + j], acc);
            // silu(x) = x * sigmoid(x)
            float s = 1.0f / (1.0f + expf(-acc));
            sh[j] = (acc * s) * w2[j];
        }
        __syncthreads();
        if (j == 0) {
            float o = 0.0f;
            for (int k = 0; k < NH; k++) o += sh[k];
            g_table[v] = o + b2[0];
        }
    }
}

// ---------------------------------------------------------------------------
// Kernel B: adjacency mask (HBM-write bound) + gather epilogue.
//   blocks [0, 64) additionally write out[i] = table[z[i]] first.
//
// Mapping: block b -> row (b >> 1), half (b & 1). Each block covers 2048
// float4 chunks (half a row); thread handles chunks tid + k*256, k=0..7
// (lane-contiguous per store -> full coalescing). Row state (band, pos_i,
// sq_i) hoisted; per-chunk fine check (j0+3>=lo && j0<hi) keeps loads/FMA
// off the instruction stream for ~99% of chunks (load-bearing: R11).
//
// __stcs (evict-first) is MANDATORY: wall-clock A/B: plain wb 180.8us /
// stcs 151.2us / stwt 153.6us. Single-pass ncu DRAM% inverted the stcs/wb
// ordering — trust graph-replay wall time for this kernel.
//
// No __launch_bounds__: R12 showed occ 60->82% was DRAM-neutral; this
// 40-reg compile is the fastest measured.
//
// In-band: d2 = (sq_i + sq_j) - 2*dot (ascending fma chain) — exact match
// of the reference's sq[:,None]+sq[None,:]-2*(pos@pos.T) rounding.
// ---------------------------------------------------------------------------
__global__ void adj_gather_kernel(const int* __restrict__ z,
                                  float* __restrict__ out,
                                  float4* __restrict__ adj) {
    if (blockIdx.x < 64) {
        int idx = blockIdx.x * 256 + threadIdx.x;
        out[idx] = g_table[z[idx]];
    }

    int row  = blockIdx.x >> 1;
    int half = blockIdx.x & 1;
    int2 band = g_band[row];
    int lo = band.x, hi = band.y;

    unsigned cbase = (unsigned)row * 4096u + (unsigned)half * 2048u; // chunk base
    int jbase = half * 8192;                                        // element base

    const float4 zero = make_float4(0.f, 0.f, 0.f, 0.f);

    // No overlap between this half-row [jbase, jbase+8192) and [lo, hi)?
    if (jbase + 8192 <= lo || jbase >= hi) {
        // Pure zero-fill fast path
#pragma unroll
        for (int k = 0; k < 8; k++)
            __stcs(&adj[cbase + threadIdx.x + k * 256], zero);
    } else {
        float xi = g_px[row], yi = g_py[row], zi = g_pz[row], sqi = g_sq[row];
#pragma unroll
        for (int k = 0; k < 8; k++) {
            int c  = threadIdx.x + k * 256;      // chunk within half-row
            int j0 = jbase + (c << 2);           // first element of chunk
            float4 v = zero;
            if (j0 + 3 >= lo && j0 < hi) {       // fine check: ~99% skip
                float r[4];
#pragma unroll
                for (int e = 0; e < 4; e++) {
                    int j = j0 + e;
                    float val = 0.0f;
                    if (j >= lo && j < hi && j != row) {
                        float dot = fmaf(zi, g_pz[j],
                                    fmaf(yi, g_py[j],
                                         __fmul_rn(xi, g_px[j])));
                        float d2 = __fsub_rn(__fadd_rn(sqi, g_sq[j]),
                                             __fmul_rn(2.0f, dot));
                        val = (d2 < 64.0f) ? 1.0f : 0.0f;
                    }
                    r[e] = val;
                }
                v = make_float4(r[0], r[1], r[2], r[3]);
            }
            __stcs(&adj[cbase + c], v);
        }
    }
}

// ---------------------------------------------------------------------------
extern "C" void kernel_launch(void* const* d_in, const int* in_sizes, int n_in,
                              void* d_out, int out_size) {
    const int*   z     = (const int*)d_in[0];
    const void*  batch = d_in[1];           // int32 or int64, device-detected
    const float* pos   = (const float*)d_in[2];
    const float* emb   = (const float*)d_in[3];
    const float* w1    = (const float*)d_in[4];
    const float* b1    = (const float*)d_in[5];
    const float* w2    = (const float*)d_in[6];
    const float* b2    = (const float*)d_in[7];
    float* out = (float*)d_out;

    fused_prep_mlp<<<164, 256>>>(batch, pos, emb, w1, b1, w2, b2);
    adj_gather_kernel<<<32768, 256>>>(z, out, (float4*)(out + NN));
}